// round 1
// baseline (speedup 1.0000x reference)
#include <cuda_runtime.h>

#define NCH 4
#define WIDTH 4096
#define HEIGHT 4096
#define NPIX (WIDTH * HEIGHT)          // 16777216 per channel
#define NTILES 64                      // 8x8
#define NBINS 256
#define CLIPV 40960                    // int(40.0 * 512*512 / 256)
#define LUTF 0.000972747802734375f     // 255 / 2^18, exact in binary

// ---------------- persistent device scratch (no allocations allowed) ----------------
static __device__ unsigned g_minb1[NCH], g_maxb1[NCH], g_mcnt[NCH];
static __device__ float    g_vmin1[NCH], g_rng1[NCH];
static __device__ int      g_cond1[NCH];
static __device__ unsigned g_hist[NCH * NTILES * NBINS];
static __device__ unsigned g_nzcnt[NCH];
static __device__ int      g_mean[NCH];
static __device__ float    g_lut[NCH * NTILES * NBINS];
static __device__ unsigned g_minb2[NCH], g_maxb2[NCH];
static __device__ float    g_vmin2[NCH], g_rng2[NCH];
static __device__ int      g_cond2[NCH];
static __device__ unsigned char g_xb[(size_t)NCH * NPIX];   // quantized bin per pixel
static __device__ unsigned char g_mk[(size_t)NCH * NPIX];   // original mask (x > 0)

// ---------------- K0: reset accumulators (graph replays must be deterministic) -------
__global__ __launch_bounds__(256) void k_init() {
    unsigned t = blockIdx.x * 256u + threadIdx.x;
    if (t < NCH * NTILES * NBINS) g_hist[t] = 0u;
    if (t < NCH) {
        g_minb1[t] = 0x7f800000u; g_maxb1[t] = 0u; g_mcnt[t] = 0u;
        g_minb2[t] = 0x7f800000u; g_maxb2[t] = 0u;
    }
}

// ---------------- K1: per-channel masked min / max / count ---------------------------
__global__ __launch_bounds__(256) void k_minmax1(const float* __restrict__ X) {
    int c = blockIdx.x >> 10;   // 1024 blocks per channel, 16384 floats per block
    const float4* p = reinterpret_cast<const float4*>(X) + (size_t)blockIdx.x * 4096u;
    float lmin = __uint_as_float(0x7f800000u);
    float lmax = 0.0f;
    unsigned cnt = 0u;
#pragma unroll
    for (int i = 0; i < 16; ++i) {
        float4 v = p[threadIdx.x + i * 256];
        if (v.x > 0.0f) { ++cnt; lmin = fminf(lmin, v.x); lmax = fmaxf(lmax, v.x); }
        if (v.y > 0.0f) { ++cnt; lmin = fminf(lmin, v.y); lmax = fmaxf(lmax, v.y); }
        if (v.z > 0.0f) { ++cnt; lmin = fminf(lmin, v.z); lmax = fmaxf(lmax, v.z); }
        if (v.w > 0.0f) { ++cnt; lmin = fminf(lmin, v.w); lmax = fmaxf(lmax, v.w); }
    }
    for (int o = 16; o; o >>= 1) {
        lmin = fminf(lmin, __shfl_xor_sync(0xffffffffu, lmin, o));
        lmax = fmaxf(lmax, __shfl_xor_sync(0xffffffffu, lmax, o));
        cnt += __shfl_xor_sync(0xffffffffu, cnt, o);
    }
    __shared__ float smn[8], smx[8];
    __shared__ unsigned scn[8];
    int w = threadIdx.x >> 5;
    if ((threadIdx.x & 31) == 0) { smn[w] = lmin; smx[w] = lmax; scn[w] = cnt; }
    __syncthreads();
    if (threadIdx.x == 0) {
        for (int i = 1; i < 8; ++i) {
            lmin = fminf(lmin, smn[i]); lmax = fmaxf(lmax, smx[i]); cnt += scn[i];
        }
        atomicMin(&g_minb1[c], __float_as_uint(lmin));   // nonneg floats: uint order == float order
        atomicMax(&g_maxb1[c], __float_as_uint(lmax));
        atomicAdd(&g_mcnt[c], cnt);
    }
}

__global__ void k_fin1() {
    int c = threadIdx.x;
    if (c >= NCH) return;
    unsigned mc = g_mcnt[c];
    float mx = __uint_as_float(g_maxb1[c]);
    float mn = __uint_as_float(g_minb1[c]);
    g_cond1[c] = (mc > 0u) && (mx > 0.0f);
    g_vmin1[c] = mn;
    g_rng1[c]  = fmaxf(mx - mn, 1e-12f);
}

// ---------------- K2: normalize, quantize, write scratch, tile histograms ------------
__device__ __forceinline__ int binone(float a, float vmin, float rng, int cond, int& mk) {
    bool m = a > 0.0f;
    mk = m ? 1 : 0;
    float x1 = m ? (cond ? (a - vmin) / rng : 0.0f) : a;
    float xf = floorf(x1 * 255.0f);
    xf = fminf(fmaxf(xf, 0.0f), 255.0f);
    return (int)xf;
}

__global__ __launch_bounds__(256) void k_binhist(const float* __restrict__ X) {
    int tx = blockIdx.x, by = blockIdx.y, c = blockIdx.z;
    int tile = (by >> 3) * 8 + tx;
    __shared__ unsigned sh[NBINS];
    sh[threadIdx.x] = 0u;
    __syncthreads();
    float vmin = g_vmin1[c], rng = g_rng1[c];
    int cond = g_cond1[c];
    size_t cb = (size_t)c * NPIX;
    for (int i = 0; i < 32; ++i) {
        int lin = i * 256 + threadIdx.x;
        int r = lin >> 7, c4 = lin & 127;
        size_t idx = cb + (size_t)(by * 64 + r) * WIDTH + tx * 512 + c4 * 4;
        float4 v = *reinterpret_cast<const float4*>(X + idx);
        int m0, m1, m2, m3;
        int b0 = binone(v.x, vmin, rng, cond, m0);
        int b1 = binone(v.y, vmin, rng, cond, m1);
        int b2 = binone(v.z, vmin, rng, cond, m2);
        int b3 = binone(v.w, vmin, rng, cond, m3);
        atomicAdd(&sh[b0], 1u);
        atomicAdd(&sh[b1], 1u);
        atomicAdd(&sh[b2], 1u);
        atomicAdd(&sh[b3], 1u);
        uchar4 xb4 = make_uchar4((unsigned char)b0, (unsigned char)b1,
                                 (unsigned char)b2, (unsigned char)b3);
        uchar4 mk4 = make_uchar4((unsigned char)m0, (unsigned char)m1,
                                 (unsigned char)m2, (unsigned char)m3);
        *reinterpret_cast<uchar4*>(g_xb + idx) = xb4;
        *reinterpret_cast<uchar4*>(g_mk + idx) = mk4;
    }
    __syncthreads();
    atomicAdd(&g_hist[(c * NTILES + tile) * NBINS + threadIdx.x], sh[threadIdx.x]);
}

// ---------------- K3a: channel-wide mean of nonzero bins ------------------------------
__global__ __launch_bounds__(256) void k_mean() {
    int c = blockIdx.x, b = threadIdx.x;
    const unsigned* h = g_hist + c * NTILES * NBINS;
    unsigned cnt = 0u;
    for (int t = 0; t < NTILES; ++t) cnt += h[t * NBINS + b];
    __shared__ unsigned long long ss[NBINS];
    __shared__ unsigned scn[NBINS];
    scn[b] = b ? cnt : 0u;
    ss[b]  = b ? (unsigned long long)cnt * (unsigned)b : 0ull;
    __syncthreads();
    for (int o = 128; o; o >>= 1) {
        if (b < o) { scn[b] += scn[b + o]; ss[b] += ss[b + o]; }
        __syncthreads();
    }
    if (b == 0) {
        g_nzcnt[c] = scn[0];
        g_mean[c]  = scn[0] ? (int)(ss[0] / scn[0]) : 0;
    }
}

// ---------------- K3b: per-tile clip, redistribute, scan, LUT -------------------------
__global__ __launch_bounds__(256) void k_lut() {
    int c = blockIdx.x >> 6, tile = blockIdx.x & 63, b = threadIdx.x;
    unsigned* hp = g_hist + (c * NTILES + tile) * NBINS;
    unsigned nz = g_nzcnt[c];
    int mean = g_mean[c];
    int h  = (int)hp[b];
    int h0 = (int)hp[0];
    if (nz > 0u) {                 // zero pixels were filled with mean_nz before histogram
        if (b == 0) h = 0;
        if (b == mean) h += h0;
    }
    int hc = min(h, CLIPV);
    int over = h - hc;
    __shared__ int red[NBINS];
    red[b] = over;
    __syncthreads();
    for (int o = 128; o; o >>= 1) {
        if (b < o) red[b] += red[b + o];
        __syncthreads();
    }
    int excess = red[0];
    int batch = excess >> 8;
    int residual = excess & 255;
    int step = residual > 0 ? max(256 / residual, 1) : 256;
    int resadd = ((b % step) == 0 && (b / step) < residual) ? 1 : 0;
    int hf = hc + batch + resadd;
    __shared__ int sc2[NBINS];
    sc2[b] = hf;
    __syncthreads();
    for (int o = 1; o < 256; o <<= 1) {       // Hillis-Steele inclusive scan (exact ints)
        int v = (b >= o) ? sc2[b - o] : 0;
        __syncthreads();
        sc2[b] += v;
        __syncthreads();
    }
    float lut = rintf((float)sc2[b] * LUTF);  // rintf == round-half-even == jnp.round
    lut = fminf(fmaxf(lut, 0.0f), 255.0f);
    g_lut[(c * NTILES + tile) * NBINS + b] = lut;
}

// ---------------- bilinear LUT interpolation (shared-staged LUT segments) -------------
__device__ __forceinline__ float interp_eq(const float (*sl)[NBINS], int xb, int col,
                                           int tx, float wy, float omy) {
    float fx = ((float)col + 0.5f) * (1.0f / 512.0f) - 0.5f;   // exact: /2^9
    float ffx = floorf(fx);
    float wx = fx - ffx;
    int x0 = min(max((int)ffx, 0), 7);
    int s0 = x0 - tx + 1;                   // slot in {0,1,2}
    int s1 = min(x0 + 1, 7) - tx + 1;
    float omx = 1.0f - wx;
    float v00 = sl[s0][xb],     v01 = sl[s1][xb];
    float v10 = sl[3 + s0][xb], v11 = sl[3 + s1][xb];
    return v00 * omy * omx + v01 * omy * wx + v10 * wy * omx + v11 * wy * wx;
}

__device__ __forceinline__ void load_luts(float (*sl)[NBINS], int c, int tx, int by) {
    int ty = by >> 3;
    int y0 = ((by & 7) < 4) ? max(ty - 1, 0) : ty;
    int y1 = min(y0 + 1, 7);
    for (int j = threadIdx.x; j < 6 * NBINS; j += 256) {
        int seg = j >> 8, b = j & 255;
        int yy = (seg < 3) ? y0 : y1;
        int xt = min(max(tx - 1 + (seg % 3), 0), 7);
        sl[seg][b] = g_lut[((c * 8 + yy) * 8 + xt) * NBINS + b];
    }
}

// ---------------- K4: min/max of eq/255 over nonzero-bin pixels ----------------------
__global__ __launch_bounds__(256) void k_minmax2() {
    int tx = blockIdx.x, by = blockIdx.y, c = blockIdx.z;
    __shared__ float sl[6][NBINS];
    load_luts(sl, c, tx, by);
    __syncthreads();
    float lmin = __uint_as_float(0x7f800000u), lmax = 0.0f;
    size_t cb = (size_t)c * NPIX;
    for (int i = 0; i < 32; ++i) {
        int lin = i * 256 + threadIdx.x;
        int r = lin >> 7, c4 = lin & 127;
        int row = by * 64 + r;
        int colb = tx * 512 + c4 * 4;
        size_t idx = cb + (size_t)row * WIDTH + colb;
        uchar4 q = *reinterpret_cast<const uchar4*>(g_xb + idx);
        float fy = ((float)row + 0.5f) * (1.0f / 512.0f) - 0.5f;
        float wy = fy - floorf(fy);
        float omy = 1.0f - wy;
        if (q.x) { float xv = interp_eq(sl, q.x, colb + 0, tx, wy, omy) / 255.0f; lmin = fminf(lmin, xv); lmax = fmaxf(lmax, xv); }
        if (q.y) { float xv = interp_eq(sl, q.y, colb + 1, tx, wy, omy) / 255.0f; lmin = fminf(lmin, xv); lmax = fmaxf(lmax, xv); }
        if (q.z) { float xv = interp_eq(sl, q.z, colb + 2, tx, wy, omy) / 255.0f; lmin = fminf(lmin, xv); lmax = fmaxf(lmax, xv); }
        if (q.w) { float xv = interp_eq(sl, q.w, colb + 3, tx, wy, omy) / 255.0f; lmin = fminf(lmin, xv); lmax = fmaxf(lmax, xv); }
    }
    for (int o = 16; o; o >>= 1) {
        lmin = fminf(lmin, __shfl_xor_sync(0xffffffffu, lmin, o));
        lmax = fmaxf(lmax, __shfl_xor_sync(0xffffffffu, lmax, o));
    }
    __shared__ float smn[8], smx[8];
    int w = threadIdx.x >> 5;
    if ((threadIdx.x & 31) == 0) { smn[w] = lmin; smx[w] = lmax; }
    __syncthreads();
    if (threadIdx.x == 0) {
        for (int i = 1; i < 8; ++i) { lmin = fminf(lmin, smn[i]); lmax = fmaxf(lmax, smx[i]); }
        atomicMin(&g_minb2[c], __float_as_uint(lmin));
        atomicMax(&g_maxb2[c], __float_as_uint(lmax));
    }
}

__global__ void k_fin2() {
    int c = threadIdx.x;
    if (c >= NCH) return;
    unsigned mc = g_mcnt[c], nz = g_nzcnt[c];
    float mn = __uint_as_float(g_minb2[c]);
    float mx = __uint_as_float(g_maxb2[c]);
    if (mc > nz) mn = fminf(mn, 0.0f);   // some masked pixel has eq==0
    g_cond2[c] = (mc > 0u) && (mx > 0.0f);
    g_vmin2[c] = mn;
    g_rng2[c]  = fmaxf(mx - mn, 1e-12f);
}

// ---------------- K5: recompute eq, final masked normalize, write output --------------
__device__ __forceinline__ float outone(int xb, int mk, const float (*sl)[NBINS], int col,
                                        int tx, float wy, float omy,
                                        float vmin, float rng, int cond) {
    const float FHL = (float)(1.0 - 1.0 / 255.0);
    const float FLO = (float)(1.0 / 255.0);
    float xv = 0.0f;
    if (xb) xv = interp_eq(sl, xb, col, tx, wy, omy) / 255.0f;
    if (mk) return cond ? ((xv - vmin) / rng) * FHL + FLO : FLO;
    return xv;
}

__global__ __launch_bounds__(256) void k_out(float* __restrict__ out) {
    int tx = blockIdx.x, by = blockIdx.y, c = blockIdx.z;
    __shared__ float sl[6][NBINS];
    load_luts(sl, c, tx, by);
    __syncthreads();
    float vmin = g_vmin2[c], rng = g_rng2[c];
    int cond = g_cond2[c];
    size_t cb = (size_t)c * NPIX;
    for (int i = 0; i < 32; ++i) {
        int lin = i * 256 + threadIdx.x;
        int r = lin >> 7, c4 = lin & 127;
        int row = by * 64 + r;
        int colb = tx * 512 + c4 * 4;
        size_t idx = cb + (size_t)row * WIDTH + colb;
        uchar4 q = *reinterpret_cast<const uchar4*>(g_xb + idx);
        uchar4 m;
        if (q.x && q.y && q.z && q.w) m = make_uchar4(1, 1, 1, 1);  // xb>0 implies masked
        else m = *reinterpret_cast<const uchar4*>(g_mk + idx);      // rare path only
        float fy = ((float)row + 0.5f) * (1.0f / 512.0f) - 0.5f;
        float wy = fy - floorf(fy);
        float omy = 1.0f - wy;
        float4 o;
        o.x = outone(q.x, m.x, sl, colb + 0, tx, wy, omy, vmin, rng, cond);
        o.y = outone(q.y, m.y, sl, colb + 1, tx, wy, omy, vmin, rng, cond);
        o.z = outone(q.z, m.z, sl, colb + 2, tx, wy, omy, vmin, rng, cond);
        o.w = outone(q.w, m.w, sl, colb + 3, tx, wy, omy, vmin, rng, cond);
        *reinterpret_cast<float4*>(out + idx) = o;
    }
}

// ---------------- launch --------------------------------------------------------------
extern "C" void kernel_launch(void* const* d_in, const int* in_sizes, int n_in,
                              void* d_out, int out_size) {
    const float* X = (const float*)d_in[0];
    float* out = (float*)d_out;
    (void)in_sizes; (void)n_in; (void)out_size;

    dim3 g(8, 64, NCH);
    k_init<<<256, 256>>>();
    k_minmax1<<<4096, 256>>>(X);
    k_fin1<<<1, 32>>>();
    k_binhist<<<g, 256>>>(X);
    k_mean<<<NCH, 256>>>();
    k_lut<<<NCH * NTILES, 256>>>();
    k_minmax2<<<g, 256>>>();
    k_fin2<<<1, 32>>>();
    k_out<<<g, 256>>>(out);
}

// round 2
// speedup vs baseline: 1.2024x; 1.2024x over previous
#include <cuda_runtime.h>

#define NCH 4
#define WIDTH 4096
#define HEIGHT 4096
#define NPIX (WIDTH * HEIGHT)          // 16777216 per channel
#define NTILES 64                      // 8x8
#define NBINS 256
#define CLIPV 40960                    // int(40.0 * 512*512 / 256)
#define LUTF 0.000972747802734375f     // 255 / 2^18, exact in binary
#define INV255 (1.0f / 255.0f)

// ---------------- persistent device scratch (no allocations allowed) ----------------
static __device__ unsigned g_minb1[NCH], g_maxb1[NCH], g_mcnt[NCH];
static __device__ float    g_vmin1[NCH], g_sc1[NCH];     // sc1 = 255/rng
static __device__ int      g_cond1[NCH];
static __device__ unsigned g_hist[NCH * NTILES * NBINS];
static __device__ unsigned g_nzcnt[NCH];
static __device__ int      g_mean[NCH];
static __device__ float    g_lut[NCH * NTILES * NBINS];
static __device__ unsigned g_minb2[NCH], g_maxb2[NCH];
static __device__ float    g_vmin2[NCH], g_irng2[NCH];
static __device__ int      g_cond2[NCH];
static __device__ unsigned char g_xb[(size_t)NCH * NPIX];        // quantized bin per pixel
static __device__ unsigned char g_mkn[(size_t)NCH * NPIX / 4];   // mask nibbles (4 px/byte)

// ---------------- K0: reset accumulators ---------------------------------------------
__global__ __launch_bounds__(256) void k_init() {
    unsigned t = blockIdx.x * 256u + threadIdx.x;
    if (t < NCH * NTILES * NBINS) g_hist[t] = 0u;
    if (t < NCH) {
        g_minb1[t] = 0x7f800000u; g_maxb1[t] = 0u; g_mcnt[t] = 0u;
        g_minb2[t] = 0x7f800000u; g_maxb2[t] = 0u;
    }
}

// ---------------- K1: per-channel masked min / max / count ---------------------------
__global__ __launch_bounds__(256) void k_minmax1(const float* __restrict__ X) {
    int c = blockIdx.x >> 10;   // 1024 blocks per channel
    const float4* p = reinterpret_cast<const float4*>(X) + (size_t)blockIdx.x * 4096u;
    float lmin = __uint_as_float(0x7f800000u);
    float lmax = 0.0f;
    unsigned cnt = 0u;
#pragma unroll 4
    for (int i = 0; i < 16; ++i) {
        float4 v = p[threadIdx.x + i * 256];
        if (v.x > 0.0f) { ++cnt; lmin = fminf(lmin, v.x); lmax = fmaxf(lmax, v.x); }
        if (v.y > 0.0f) { ++cnt; lmin = fminf(lmin, v.y); lmax = fmaxf(lmax, v.y); }
        if (v.z > 0.0f) { ++cnt; lmin = fminf(lmin, v.z); lmax = fmaxf(lmax, v.z); }
        if (v.w > 0.0f) { ++cnt; lmin = fminf(lmin, v.w); lmax = fmaxf(lmax, v.w); }
    }
    for (int o = 16; o; o >>= 1) {
        lmin = fminf(lmin, __shfl_xor_sync(0xffffffffu, lmin, o));
        lmax = fmaxf(lmax, __shfl_xor_sync(0xffffffffu, lmax, o));
        cnt += __shfl_xor_sync(0xffffffffu, cnt, o);
    }
    __shared__ float smn[8], smx[8];
    __shared__ unsigned scn[8];
    int w = threadIdx.x >> 5;
    if ((threadIdx.x & 31) == 0) { smn[w] = lmin; smx[w] = lmax; scn[w] = cnt; }
    __syncthreads();
    if (threadIdx.x == 0) {
        for (int i = 1; i < 8; ++i) {
            lmin = fminf(lmin, smn[i]); lmax = fmaxf(lmax, smx[i]); cnt += scn[i];
        }
        atomicMin(&g_minb1[c], __float_as_uint(lmin));   // nonneg floats: uint order == float order
        atomicMax(&g_maxb1[c], __float_as_uint(lmax));
        atomicAdd(&g_mcnt[c], cnt);
    }
}

__global__ void k_fin1() {
    int c = threadIdx.x;
    if (c >= NCH) return;
    unsigned mc = g_mcnt[c];
    float mx = __uint_as_float(g_maxb1[c]);
    float mn = __uint_as_float(g_minb1[c]);
    g_cond1[c] = (mc > 0u) && (mx > 0.0f);
    g_vmin1[c] = mn;
    g_sc1[c]   = 255.0f / fmaxf(mx - mn, 1e-12f);
}

// ---------------- K2: normalize, quantize, write scratch, tile histograms ------------
__device__ __forceinline__ int binone(float a, float vmin, float sc, int cond, int& mk) {
    bool m = a > 0.0f;
    mk = m ? 1 : 0;
    float xf = floorf(m ? (cond ? (a - vmin) * sc : 0.0f) : a * 255.0f);
    xf = fminf(fmaxf(xf, 0.0f), 255.0f);
    return (int)xf;
}

__global__ __launch_bounds__(256) void k_binhist(const float* __restrict__ X) {
    int tx = blockIdx.x, by = blockIdx.y, c = blockIdx.z;
    int tile = (by >> 3) * 8 + tx;
    __shared__ unsigned sh[NBINS];
    sh[threadIdx.x] = 0u;
    __syncthreads();
    float vmin = g_vmin1[c], sc = g_sc1[c];
    int cond = g_cond1[c];
    size_t cb = (size_t)c * NPIX;
#pragma unroll 4
    for (int i = 0; i < 32; ++i) {
        int lin = i * 256 + threadIdx.x;
        int r = lin >> 7, c4 = lin & 127;
        size_t idx = cb + (size_t)(by * 64 + r) * WIDTH + tx * 512 + c4 * 4;
        float4 v = *reinterpret_cast<const float4*>(X + idx);
        int m0, m1, m2, m3;
        int b0 = binone(v.x, vmin, sc, cond, m0);
        int b1 = binone(v.y, vmin, sc, cond, m1);
        int b2 = binone(v.z, vmin, sc, cond, m2);
        int b3 = binone(v.w, vmin, sc, cond, m3);
        atomicAdd(&sh[b0], 1u);
        atomicAdd(&sh[b1], 1u);
        atomicAdd(&sh[b2], 1u);
        atomicAdd(&sh[b3], 1u);
        *reinterpret_cast<uchar4*>(g_xb + idx) =
            make_uchar4((unsigned char)b0, (unsigned char)b1,
                        (unsigned char)b2, (unsigned char)b3);
        g_mkn[idx >> 2] = (unsigned char)(m0 | (m1 << 1) | (m2 << 2) | (m3 << 3));
    }
    __syncthreads();
    atomicAdd(&g_hist[(c * NTILES + tile) * NBINS + threadIdx.x], sh[threadIdx.x]);
}

// ---------------- K3a: channel-wide mean of nonzero bins ------------------------------
__global__ __launch_bounds__(256) void k_mean() {
    int c = blockIdx.x, b = threadIdx.x;
    const unsigned* h = g_hist + c * NTILES * NBINS;
    unsigned cnt = 0u;
    for (int t = 0; t < NTILES; ++t) cnt += h[t * NBINS + b];
    __shared__ unsigned long long ss[NBINS];
    __shared__ unsigned scn[NBINS];
    scn[b] = b ? cnt : 0u;
    ss[b]  = b ? (unsigned long long)cnt * (unsigned)b : 0ull;
    __syncthreads();
    for (int o = 128; o; o >>= 1) {
        if (b < o) { scn[b] += scn[b + o]; ss[b] += ss[b + o]; }
        __syncthreads();
    }
    if (b == 0) {
        g_nzcnt[c] = scn[0];
        g_mean[c]  = scn[0] ? (int)(ss[0] / scn[0]) : 0;
    }
}

// ---------------- K3b: per-tile clip, redistribute, scan, LUT -------------------------
__global__ __launch_bounds__(256) void k_lut() {
    int c = blockIdx.x >> 6, tile = blockIdx.x & 63, b = threadIdx.x;
    unsigned* hp = g_hist + (c * NTILES + tile) * NBINS;
    unsigned nz = g_nzcnt[c];
    int mean = g_mean[c];
    int h  = (int)hp[b];
    int h0 = (int)hp[0];
    if (nz > 0u) {                 // zero pixels were filled with mean_nz before histogram
        if (b == 0) h = 0;
        if (b == mean) h += h0;
    }
    int hc = min(h, CLIPV);
    int over = h - hc;
    __shared__ int red[NBINS];
    red[b] = over;
    __syncthreads();
    for (int o = 128; o; o >>= 1) {
        if (b < o) red[b] += red[b + o];
        __syncthreads();
    }
    int excess = red[0];
    int batch = excess >> 8;
    int residual = excess & 255;
    int step = residual > 0 ? max(256 / residual, 1) : 256;
    int resadd = ((b % step) == 0 && (b / step) < residual) ? 1 : 0;
    int hf = hc + batch + resadd;
    __shared__ int sc2[NBINS];
    sc2[b] = hf;
    __syncthreads();
    for (int o = 1; o < 256; o <<= 1) {       // Hillis-Steele inclusive scan (exact ints)
        int v = (b >= o) ? sc2[b - o] : 0;
        __syncthreads();
        sc2[b] += v;
        __syncthreads();
    }
    float lut = rintf((float)sc2[b] * LUTF);  // rintf == round-half-even == jnp.round
    lut = fminf(fmaxf(lut, 0.0f), 255.0f);
    g_lut[(c * NTILES + tile) * NBINS + b] = lut;
}

// ---------------- bilinear LUT interpolation, float2-packed (y0,y1) tables ------------
// Per 64-row block, y0/y1 are fixed, so each (cell, bin) packs L[y0] and L[y1] together:
// 2 x LDS.64 per pixel instead of 4 x LDS.32.
__device__ __forceinline__ float interp_eq(const float2 (*sl)[NBINS], int xb, int col,
                                           int tx, float wy, float omy) {
    float fx = ((float)col + 0.5f) * (1.0f / 512.0f) - 0.5f;   // exact: /2^9
    float ffx = floorf(fx);
    float wx = fx - ffx;
    int x0 = min(max((int)ffx, 0), 7);
    int s0 = x0 - tx + 1;                   // slot in {0,1,2}
    int s1 = min(x0 + 1, 7) - tx + 1;
    float2 va = sl[s0][xb];
    float2 vb = sl[s1][xb];
    float ya = omy * va.x + wy * va.y;
    float yb = omy * vb.x + wy * vb.y;
    return ya + wx * (yb - ya);
}

__device__ __forceinline__ void load_luts(float2 (*sl)[NBINS], int c, int tx, int by) {
    int ty = by >> 3;
    int y0 = ((by & 7) < 4) ? max(ty - 1, 0) : ty;
    int y1 = min(y0 + 1, 7);
    for (int j = threadIdx.x; j < 3 * NBINS; j += 256) {
        int seg = j >> 8, b = j & 255;
        int xt = min(max(tx - 1 + seg, 0), 7);
        float a0 = g_lut[((c * 8 + y0) * 8 + xt) * NBINS + b];
        float a1 = g_lut[((c * 8 + y1) * 8 + xt) * NBINS + b];
        sl[seg][b] = make_float2(a0, a1);
    }
}

// ---------------- K4: min/max of eq/255 over nonzero-bin pixels ----------------------
__global__ __launch_bounds__(256) void k_minmax2() {
    int tx = blockIdx.x, by = blockIdx.y, c = blockIdx.z;
    __shared__ float2 sl[3][NBINS];
    load_luts(sl, c, tx, by);
    __syncthreads();
    float lmin = __uint_as_float(0x7f800000u), lmax = 0.0f;
    size_t cb = (size_t)c * NPIX;
#pragma unroll 4
    for (int i = 0; i < 32; ++i) {
        int lin = i * 256 + threadIdx.x;
        int r = lin >> 7, c4 = lin & 127;
        int row = by * 64 + r;
        int colb = tx * 512 + c4 * 4;
        size_t idx = cb + (size_t)row * WIDTH + colb;
        uchar4 q = *reinterpret_cast<const uchar4*>(g_xb + idx);
        float fy = ((float)row + 0.5f) * (1.0f / 512.0f) - 0.5f;
        float wy = fy - floorf(fy);
        float omy = 1.0f - wy;
        if (q.x) { float xv = interp_eq(sl, q.x, colb + 0, tx, wy, omy) * INV255; lmin = fminf(lmin, xv); lmax = fmaxf(lmax, xv); }
        if (q.y) { float xv = interp_eq(sl, q.y, colb + 1, tx, wy, omy) * INV255; lmin = fminf(lmin, xv); lmax = fmaxf(lmax, xv); }
        if (q.z) { float xv = interp_eq(sl, q.z, colb + 2, tx, wy, omy) * INV255; lmin = fminf(lmin, xv); lmax = fmaxf(lmax, xv); }
        if (q.w) { float xv = interp_eq(sl, q.w, colb + 3, tx, wy, omy) * INV255; lmin = fminf(lmin, xv); lmax = fmaxf(lmax, xv); }
    }
    for (int o = 16; o; o >>= 1) {
        lmin = fminf(lmin, __shfl_xor_sync(0xffffffffu, lmin, o));
        lmax = fmaxf(lmax, __shfl_xor_sync(0xffffffffu, lmax, o));
    }
    __shared__ float smn[8], smx[8];
    int w = threadIdx.x >> 5;
    if ((threadIdx.x & 31) == 0) { smn[w] = lmin; smx[w] = lmax; }
    __syncthreads();
    if (threadIdx.x == 0) {
        for (int i = 1; i < 8; ++i) { lmin = fminf(lmin, smn[i]); lmax = fmaxf(lmax, smx[i]); }
        atomicMin(&g_minb2[c], __float_as_uint(lmin));
        atomicMax(&g_maxb2[c], __float_as_uint(lmax));
    }
}

__global__ void k_fin2() {
    int c = threadIdx.x;
    if (c >= NCH) return;
    unsigned mc = g_mcnt[c], nz = g_nzcnt[c];
    float mn = __uint_as_float(g_minb2[c]);
    float mx = __uint_as_float(g_maxb2[c]);
    if (mc > nz) mn = fminf(mn, 0.0f);   // some masked pixel has eq==0
    g_cond2[c] = (mc > 0u) && (mx > 0.0f);
    g_vmin2[c] = mn;
    g_irng2[c] = 1.0f / fmaxf(mx - mn, 1e-12f);
}

// ---------------- K5: recompute eq, final masked normalize, write output --------------
__device__ __forceinline__ float outone(int xb, int mk, const float2 (*sl)[NBINS], int col,
                                        int tx, float wy, float omy,
                                        float vmin, float irng, int cond) {
    const float FHL = (float)(1.0 - 1.0 / 255.0);
    const float FLO = (float)(1.0 / 255.0);
    float xv = 0.0f;
    if (xb) xv = interp_eq(sl, xb, col, tx, wy, omy) * INV255;
    if (mk) return cond ? ((xv - vmin) * irng) * FHL + FLO : FLO;
    return xv;
}

__global__ __launch_bounds__(256) void k_out(float* __restrict__ out) {
    int tx = blockIdx.x, by = blockIdx.y, c = blockIdx.z;
    __shared__ float2 sl[3][NBINS];
    load_luts(sl, c, tx, by);
    __syncthreads();
    float vmin = g_vmin2[c], irng = g_irng2[c];
    int cond = g_cond2[c];
    size_t cb = (size_t)c * NPIX;
#pragma unroll 4
    for (int i = 0; i < 32; ++i) {
        int lin = i * 256 + threadIdx.x;
        int r = lin >> 7, c4 = lin & 127;
        int row = by * 64 + r;
        int colb = tx * 512 + c4 * 4;
        size_t idx = cb + (size_t)row * WIDTH + colb;
        uchar4 q = *reinterpret_cast<const uchar4*>(g_xb + idx);
        uchar4 m;
        if (q.x && q.y && q.z && q.w) {
            m = make_uchar4(1, 1, 1, 1);                      // xb>0 implies masked
        } else {
            unsigned char mb = g_mkn[idx >> 2];               // rare path only
            m = make_uchar4(mb & 1, (mb >> 1) & 1, (mb >> 2) & 1, (mb >> 3) & 1);
        }
        float fy = ((float)row + 0.5f) * (1.0f / 512.0f) - 0.5f;
        float wy = fy - floorf(fy);
        float omy = 1.0f - wy;
        float4 o;
        o.x = outone(q.x, m.x, sl, colb + 0, tx, wy, omy, vmin, irng, cond);
        o.y = outone(q.y, m.y, sl, colb + 1, tx, wy, omy, vmin, irng, cond);
        o.z = outone(q.z, m.z, sl, colb + 2, tx, wy, omy, vmin, irng, cond);
        o.w = outone(q.w, m.w, sl, colb + 3, tx, wy, omy, vmin, irng, cond);
        *reinterpret_cast<float4*>(out + idx) = o;
    }
}

// ---------------- launch --------------------------------------------------------------
extern "C" void kernel_launch(void* const* d_in, const int* in_sizes, int n_in,
                              void* d_out, int out_size) {
    const float* X = (const float*)d_in[0];
    float* out = (float*)d_out;
    (void)in_sizes; (void)n_in; (void)out_size;

    dim3 g(8, 64, NCH);
    k_init<<<256, 256>>>();
    k_minmax1<<<4096, 256>>>(X);
    k_fin1<<<1, 32>>>();
    k_binhist<<<g, 256>>>(X);
    k_mean<<<NCH, 256>>>();
    k_lut<<<NCH * NTILES, 256>>>();
    k_minmax2<<<g, 256>>>();
    k_fin2<<<1, 32>>>();
    k_out<<<g, 256>>>(out);
}

// round 3
// speedup vs baseline: 1.4560x; 1.2109x over previous
#include <cuda_runtime.h>

#define NCH 4
#define WIDTH 4096
#define HEIGHT 4096
#define NPIX (WIDTH * HEIGHT)          // 16777216 per channel
#define NTILES 64                      // 8x8
#define NBINS 256
#define CLIPV 40960                    // int(40.0 * 512*512 / 256)
#define LUTF 0.000972747802734375f     // 255 / 2^18, exact in binary
#define INV255 (1.0f / 255.0f)

// ---------------- persistent device scratch (no allocations allowed) ----------------
static __device__ unsigned g_minb1[NCH], g_maxb1[NCH], g_mcnt[NCH];
static __device__ float    g_sc1[NCH], g_off1[NCH];      // bin = trunc(a*sc + off)
static __device__ int      g_cond1[NCH];
static __device__ unsigned g_hist[NCH * NTILES * NBINS];
static __device__ unsigned g_nzcnt[NCH];
static __device__ int      g_mean[NCH];
static __device__ float    g_lut[NCH * NTILES * NBINS];  // exact integers 0..255
static __device__ unsigned g_minb2[NCH], g_maxb2[NCH];   // min/max on eq scale [0,255]
static __device__ float    g_A[NCH], g_B[NCH];           // out = fmaf(eq, A, B) for masked
static __device__ unsigned char g_xb[(size_t)NCH * NPIX]; // quantized bin per pixel

// ---------------- K0: reset accumulators ---------------------------------------------
__global__ __launch_bounds__(256) void k_init() {
    unsigned t = blockIdx.x * 256u + threadIdx.x;
    if (t < NCH * NTILES * NBINS) g_hist[t] = 0u;
    if (t < NCH) {
        g_minb1[t] = 0x7f800000u; g_maxb1[t] = 0u; g_mcnt[t] = 0u;
        g_minb2[t] = 0x7f800000u; g_maxb2[t] = 0u;
    }
}

// ---------------- K1: per-channel masked min / max / count ---------------------------
__global__ __launch_bounds__(256) void k_minmax1(const float* __restrict__ X) {
    int c = blockIdx.x >> 10;   // 1024 blocks per channel
    const float4* p = reinterpret_cast<const float4*>(X) + (size_t)blockIdx.x * 4096u;
    float lmin = __uint_as_float(0x7f800000u);
    float lmax = 0.0f;
    unsigned cnt = 0u;
#pragma unroll 4
    for (int i = 0; i < 16; ++i) {
        float4 v = p[threadIdx.x + i * 256];
        if (v.x > 0.0f) { ++cnt; lmin = fminf(lmin, v.x); lmax = fmaxf(lmax, v.x); }
        if (v.y > 0.0f) { ++cnt; lmin = fminf(lmin, v.y); lmax = fmaxf(lmax, v.y); }
        if (v.z > 0.0f) { ++cnt; lmin = fminf(lmin, v.z); lmax = fmaxf(lmax, v.z); }
        if (v.w > 0.0f) { ++cnt; lmin = fminf(lmin, v.w); lmax = fmaxf(lmax, v.w); }
    }
    for (int o = 16; o; o >>= 1) {
        lmin = fminf(lmin, __shfl_xor_sync(0xffffffffu, lmin, o));
        lmax = fmaxf(lmax, __shfl_xor_sync(0xffffffffu, lmax, o));
        cnt += __shfl_xor_sync(0xffffffffu, cnt, o);
    }
    __shared__ float smn[8], smx[8];
    __shared__ unsigned scn[8];
    int w = threadIdx.x >> 5;
    if ((threadIdx.x & 31) == 0) { smn[w] = lmin; smx[w] = lmax; scn[w] = cnt; }
    __syncthreads();
    if (threadIdx.x == 0) {
        for (int i = 1; i < 8; ++i) {
            lmin = fminf(lmin, smn[i]); lmax = fmaxf(lmax, smx[i]); cnt += scn[i];
        }
        atomicMin(&g_minb1[c], __float_as_uint(lmin));   // nonneg floats: uint order == float order
        atomicMax(&g_maxb1[c], __float_as_uint(lmax));
        atomicAdd(&g_mcnt[c], cnt);
    }
}

__global__ void k_fin1() {
    int c = threadIdx.x;
    if (c >= NCH) return;
    unsigned mc = g_mcnt[c];
    float mx = __uint_as_float(g_maxb1[c]);
    float mn = __uint_as_float(g_minb1[c]);
    g_cond1[c] = (mc > 0u) && (mx > 0.0f);
    double rng = fmax((double)mx - (double)mn, 1e-12);
    double sc = 255.0 / rng;
    g_sc1[c]  = (float)sc;
    g_off1[c] = (float)(-(double)mn * sc);
}

// ---------------- K2: normalize, quantize, write bins, tile histograms ---------------
__device__ __forceinline__ unsigned binone(float a, float sc, float off, int cond) {
    float xm = cond ? fmaf(a, sc, off) : 0.0f;
    float x  = a > 0.0f ? xm : a * 255.0f;
    return __float2uint_rz(fminf(x, 255.0f));   // F2I.U32 saturates negatives to 0
}

__global__ __launch_bounds__(256) void k_binhist(const float* __restrict__ X) {
    int tx = blockIdx.x, by = blockIdx.y, c = blockIdx.z;
    int tile = (by >> 3) * 8 + tx;
    __shared__ unsigned sh[NBINS];
    sh[threadIdx.x] = 0u;
    __syncthreads();
    float sc = g_sc1[c], off = g_off1[c];
    int cond = g_cond1[c];
    size_t cb = (size_t)c * NPIX;
#pragma unroll 4
    for (int i = 0; i < 32; ++i) {
        int lin = i * 256 + threadIdx.x;
        int r = lin >> 7, c4 = lin & 127;
        size_t idx = cb + (size_t)(by * 64 + r) * WIDTH + tx * 512 + c4 * 4;
        float4 v = *reinterpret_cast<const float4*>(X + idx);
        unsigned b0 = binone(v.x, sc, off, cond);
        unsigned b1 = binone(v.y, sc, off, cond);
        unsigned b2 = binone(v.z, sc, off, cond);
        unsigned b3 = binone(v.w, sc, off, cond);
        atomicAdd(&sh[b0], 1u);
        atomicAdd(&sh[b1], 1u);
        atomicAdd(&sh[b2], 1u);
        atomicAdd(&sh[b3], 1u);
        *reinterpret_cast<unsigned*>(g_xb + idx) = b0 | (b1 << 8) | (b2 << 16) | (b3 << 24);
    }
    __syncthreads();
    atomicAdd(&g_hist[(c * NTILES + tile) * NBINS + threadIdx.x], sh[threadIdx.x]);
}

// ---------------- K3a: channel-wide mean of nonzero bins ------------------------------
__global__ __launch_bounds__(256) void k_mean() {
    int c = blockIdx.x, b = threadIdx.x;
    const unsigned* h = g_hist + c * NTILES * NBINS;
    unsigned cnt = 0u;
    for (int t = 0; t < NTILES; ++t) cnt += h[t * NBINS + b];
    __shared__ unsigned long long ss[NBINS];
    __shared__ unsigned scn[NBINS];
    scn[b] = b ? cnt : 0u;
    ss[b]  = b ? (unsigned long long)cnt * (unsigned)b : 0ull;
    __syncthreads();
    for (int o = 128; o; o >>= 1) {
        if (b < o) { scn[b] += scn[b + o]; ss[b] += ss[b + o]; }
        __syncthreads();
    }
    if (b == 0) {
        g_nzcnt[c] = scn[0];
        g_mean[c]  = scn[0] ? (int)(ss[0] / scn[0]) : 0;
    }
}

// ---------------- K3b: per-tile clip, redistribute, scan, LUT -------------------------
__global__ __launch_bounds__(256) void k_lut() {
    int c = blockIdx.x >> 6, tile = blockIdx.x & 63, b = threadIdx.x;
    unsigned* hp = g_hist + (c * NTILES + tile) * NBINS;
    unsigned nz = g_nzcnt[c];
    int mean = g_mean[c];
    int h  = (int)hp[b];
    int h0 = (int)hp[0];
    if (nz > 0u) {                 // zero pixels were filled with mean_nz before histogram
        if (b == 0) h = 0;
        if (b == mean) h += h0;
    }
    int hc = min(h, CLIPV);
    int over = h - hc;
    __shared__ int red[NBINS];
    red[b] = over;
    __syncthreads();
    for (int o = 128; o; o >>= 1) {
        if (b < o) red[b] += red[b + o];
        __syncthreads();
    }
    int excess = red[0];
    int batch = excess >> 8;
    int residual = excess & 255;
    int step = residual > 0 ? max(256 / residual, 1) : 256;
    int resadd = ((b % step) == 0 && (b / step) < residual) ? 1 : 0;
    int hf = hc + batch + resadd;
    __shared__ int sc2[NBINS];
    sc2[b] = hf;
    __syncthreads();
    for (int o = 1; o < 256; o <<= 1) {       // Hillis-Steele inclusive scan (exact ints)
        int v = (b >= o) ? sc2[b - o] : 0;
        __syncthreads();
        sc2[b] += v;
        __syncthreads();
    }
    float lut = rintf((float)sc2[b] * LUTF);  // rintf == round-half-even == jnp.round
    lut = fminf(fmaxf(lut, 0.0f), 255.0f);
    g_lut[(c * NTILES + tile) * NBINS + b] = lut;
}

// ---------------- combined 4-point stencil table: one uint per (x-slot, bin) ----------
// Per 64-row block (by) the y-pair (y0,y1) is fixed, and per column s0 in {0,1}.
// sl[s][bin] packs (L[y0][cell s], L[y1][cell s], L[y0][cell s+1], L[y1][cell s+1])
// as 4 exact uchar values -> ONE LDS.32 per pixel fetches the whole bilinear stencil.
__device__ __forceinline__ void load_cmb(unsigned (*sl)[NBINS], int c, int tx, int by) {
    int ty = by >> 3;
    int y0 = ((by & 7) < 4) ? max(ty - 1, 0) : ty;
    int y1 = min(y0 + 1, 7);
    const float* L0 = g_lut + ((c * 8 + y0) * 8) * NBINS;
    const float* L1 = g_lut + ((c * 8 + y1) * 8) * NBINS;
    int b = threadIdx.x;   // 256 threads == 256 bins
#pragma unroll
    for (int s = 0; s < 2; ++s) {
        int xa = min(max(tx - 1 + s, 0), 7);
        int xb_ = min(tx + s, 7);
        unsigned v00 = (unsigned)L0[xa * NBINS + b];
        unsigned v10 = (unsigned)L1[xa * NBINS + b];
        unsigned v01 = (unsigned)L0[xb_ * NBINS + b];
        unsigned v11 = (unsigned)L1[xb_ * NBINS + b];
        sl[s][b] = v00 | (v10 << 8) | (v01 << 16) | (v11 << 24);
    }
}

__device__ __forceinline__ float eq4(unsigned w, float wx, float wy, float omy) {
    float v00 = (float)(w & 0xffu);
    float v10 = (float)((w >> 8) & 0xffu);
    float v01 = (float)((w >> 16) & 0xffu);
    float v11 = (float)(w >> 24);
    float ya = omy * v00 + wy * v10;
    float yb = omy * v01 + wy * v11;
    return ya + wx * (yb - ya);
}

// ---------------- K4: min/max of eq (0..255 scale) over nonzero-bin pixels ------------
__global__ __launch_bounds__(256) void k_minmax2() {
    int tx = blockIdx.x, by = blockIdx.y, c = blockIdx.z;
    __shared__ unsigned sl[2][NBINS];
    load_cmb(sl, c, tx, by);
    __syncthreads();
    int c4 = threadIdx.x & 127;
    int colb = tx * 512 + c4 * 4;
    float wx[4]; const unsigned* slp[4];
#pragma unroll
    for (int k = 0; k < 4; ++k) {
        float fx = ((float)(colb + k) + 0.5f) * (1.0f / 512.0f) - 0.5f;
        float ff = floorf(fx);
        wx[k] = fx - ff;
        int x0 = min(max((int)ff, 0), 7);
        slp[k] = sl[x0 - tx + 1];
    }
    int r0 = threadIdx.x >> 7;
    size_t base = (size_t)c * NPIX + (size_t)(by * 64 + r0) * WIDTH + colb;
    float emin = __uint_as_float(0x7f800000u), emax = 0.0f;
#pragma unroll 4
    for (int i = 0; i < 32; ++i) {
        int row = by * 64 + i * 2 + r0;
        float fy = ((float)row + 0.5f) * (1.0f / 512.0f) - 0.5f;
        float wy = fy - floorf(fy);
        float omy = 1.0f - wy;
        uchar4 q = *reinterpret_cast<const uchar4*>(g_xb + base + (size_t)i * (2 * WIDTH));
        if (q.x) { float e = eq4(slp[0][q.x], wx[0], wy, omy); emin = fminf(emin, e); emax = fmaxf(emax, e); }
        if (q.y) { float e = eq4(slp[1][q.y], wx[1], wy, omy); emin = fminf(emin, e); emax = fmaxf(emax, e); }
        if (q.z) { float e = eq4(slp[2][q.z], wx[2], wy, omy); emin = fminf(emin, e); emax = fmaxf(emax, e); }
        if (q.w) { float e = eq4(slp[3][q.w], wx[3], wy, omy); emin = fminf(emin, e); emax = fmaxf(emax, e); }
    }
    for (int o = 16; o; o >>= 1) {
        emin = fminf(emin, __shfl_xor_sync(0xffffffffu, emin, o));
        emax = fmaxf(emax, __shfl_xor_sync(0xffffffffu, emax, o));
    }
    __shared__ float smn[8], smx[8];
    int w = threadIdx.x >> 5;
    if ((threadIdx.x & 31) == 0) { smn[w] = emin; smx[w] = emax; }
    __syncthreads();
    if (threadIdx.x == 0) {
        for (int i = 1; i < 8; ++i) { emin = fminf(emin, smn[i]); emax = fmaxf(emax, smx[i]); }
        atomicMin(&g_minb2[c], __float_as_uint(emin));
        atomicMax(&g_maxb2[c], __float_as_uint(emax));
    }
}

__global__ void k_fin2() {
    int c = threadIdx.x;
    if (c >= NCH) return;
    unsigned mc = g_mcnt[c], nz = g_nzcnt[c];
    float mn = __uint_as_float(g_minb2[c]) / 255.0f;   // exact: matches per-pixel eq/255 min
    float mx = __uint_as_float(g_maxb2[c]) / 255.0f;
    if (mc > nz) mn = fminf(mn, 0.0f);   // some masked pixel has eq==0
    int cond = (mc > 0u) && (mx > 0.0f);
    if (cond) {
        double irng = 1.0 / fmax((double)mx - (double)mn, 1e-12);
        double fhl = 1.0 - 1.0 / 255.0;
        g_A[c] = (float)((1.0 / 255.0) * irng * fhl);            // out = eq*A + B
        g_B[c] = (float)((1.0 / 255.0) - (double)mn * irng * fhl);
    } else {
        g_A[c] = 0.0f;
        g_B[c] = INV255;
    }
}

// ---------------- K5: recompute eq, final masked normalize, write output --------------
__global__ __launch_bounds__(256) void k_out(const float* __restrict__ X,
                                             float* __restrict__ out) {
    int tx = blockIdx.x, by = blockIdx.y, c = blockIdx.z;
    __shared__ unsigned sl[2][NBINS];
    load_cmb(sl, c, tx, by);
    __syncthreads();
    float A = g_A[c], B = g_B[c];
    int c4 = threadIdx.x & 127;
    int colb = tx * 512 + c4 * 4;
    float wx[4]; const unsigned* slp[4];
#pragma unroll
    for (int k = 0; k < 4; ++k) {
        float fx = ((float)(colb + k) + 0.5f) * (1.0f / 512.0f) - 0.5f;
        float ff = floorf(fx);
        wx[k] = fx - ff;
        int x0 = min(max((int)ff, 0), 7);
        slp[k] = sl[x0 - tx + 1];
    }
    int r0 = threadIdx.x >> 7;
    size_t base = (size_t)c * NPIX + (size_t)(by * 64 + r0) * WIDTH + colb;
#pragma unroll 4
    for (int i = 0; i < 32; ++i) {
        int row = by * 64 + i * 2 + r0;
        float fy = ((float)row + 0.5f) * (1.0f / 512.0f) - 0.5f;
        float wy = fy - floorf(fy);
        float omy = 1.0f - wy;
        size_t idx = base + (size_t)i * (2 * WIDTH);
        uchar4 q = *reinterpret_cast<const uchar4*>(g_xb + idx);
        float4 o;
        if (min(min(q.x, q.y), min(q.z, q.w)) != 0) {            // fast path: all masked
            o.x = fmaf(eq4(slp[0][q.x], wx[0], wy, omy), A, B);
            o.y = fmaf(eq4(slp[1][q.y], wx[1], wy, omy), A, B);
            o.z = fmaf(eq4(slp[2][q.z], wx[2], wy, omy), A, B);
            o.w = fmaf(eq4(slp[3][q.w], wx[3], wy, omy), A, B);
        } else {                                                  // rare: recover mask from X
            float4 v = *reinterpret_cast<const float4*>(X + idx);
            o.x = q.x ? fmaf(eq4(slp[0][q.x], wx[0], wy, omy), A, B) : (v.x > 0.0f ? B : 0.0f);
            o.y = q.y ? fmaf(eq4(slp[1][q.y], wx[1], wy, omy), A, B) : (v.y > 0.0f ? B : 0.0f);
            o.z = q.z ? fmaf(eq4(slp[2][q.z], wx[2], wy, omy), A, B) : (v.z > 0.0f ? B : 0.0f);
            o.w = q.w ? fmaf(eq4(slp[3][q.w], wx[3], wy, omy), A, B) : (v.w > 0.0f ? B : 0.0f);
        }
        *reinterpret_cast<float4*>(out + idx) = o;
    }
}

// ---------------- launch --------------------------------------------------------------
extern "C" void kernel_launch(void* const* d_in, const int* in_sizes, int n_in,
                              void* d_out, int out_size) {
    const float* X = (const float*)d_in[0];
    float* out = (float*)d_out;
    (void)in_sizes; (void)n_in; (void)out_size;

    dim3 g(8, 64, NCH);
    k_init<<<256, 256>>>();
    k_minmax1<<<4096, 256>>>(X);
    k_fin1<<<1, 32>>>();
    k_binhist<<<g, 256>>>(X);
    k_mean<<<NCH, 256>>>();
    k_lut<<<NCH * NTILES, 256>>>();
    k_minmax2<<<g, 256>>>();
    k_fin2<<<1, 32>>>();
    k_out<<<g, 256>>>(X, out);
}

// round 4
// speedup vs baseline: 1.5015x; 1.0313x over previous
#include <cuda_runtime.h>

#define NCH 4
#define WIDTH 4096
#define HEIGHT 4096
#define NPIX (WIDTH * HEIGHT)          // 16777216 per channel
#define NTILES 64                      // 8x8
#define NBINS 256
#define CLIPV 40960                    // int(40.0 * 512*512 / 256)
#define LUTF 0.000972747802734375f     // 255 / 2^18, exact in binary
#define INV255 (1.0f / 255.0f)

// ------------- persistent device scratch: self-cleaning across graph replays ---------
// Invariant: every accumulator is back to its initial value by the end of each
// kernel_launch call (reset happens right after the last read of each value).
static __device__ unsigned g_minb1[NCH] = {0x7f800000u, 0x7f800000u, 0x7f800000u, 0x7f800000u};
static __device__ unsigned g_maxb1[NCH];                 // zero-init
static __device__ unsigned g_mcnt[NCH];                  // zero-init
static __device__ unsigned g_ctr1, g_ctr2;               // zero-init, wrap via atomicInc
static __device__ float    g_sc1[NCH], g_off1[NCH];      // bin = trunc(a*sc + off)
static __device__ int      g_cond1[NCH];
static __device__ unsigned g_hist[NCH * NTILES * NBINS]; // zero-init; re-zeroed in k_minmax2
static __device__ unsigned g_nzcnt[NCH];
static __device__ float    g_lut[NCH * NTILES * NBINS];  // exact integers 0..255
static __device__ unsigned g_minb2[NCH] = {0x7f800000u, 0x7f800000u, 0x7f800000u, 0x7f800000u};
static __device__ unsigned g_maxb2[NCH];                 // zero-init
static __device__ float    g_A[NCH], g_B[NCH];           // out = fmaf(eq, A, B) for masked
static __device__ unsigned char g_xb[(size_t)NCH * NPIX]; // quantized bin per pixel

// ---------------- K1: masked min/max/count + fused finalize (last block) -------------
__global__ __launch_bounds__(256) void k_minmax1(const float* __restrict__ X) {
    int c = blockIdx.x >> 10;   // 1024 blocks per channel
    const float4* p = reinterpret_cast<const float4*>(X) + (size_t)blockIdx.x * 4096u;
    float lmin = __uint_as_float(0x7f800000u);
    float lmax = 0.0f;
    unsigned cnt = 0u;
#pragma unroll 4
    for (int i = 0; i < 16; ++i) {
        float4 v = p[threadIdx.x + i * 256];
        if (v.x > 0.0f) { ++cnt; lmin = fminf(lmin, v.x); lmax = fmaxf(lmax, v.x); }
        if (v.y > 0.0f) { ++cnt; lmin = fminf(lmin, v.y); lmax = fmaxf(lmax, v.y); }
        if (v.z > 0.0f) { ++cnt; lmin = fminf(lmin, v.z); lmax = fmaxf(lmax, v.z); }
        if (v.w > 0.0f) { ++cnt; lmin = fminf(lmin, v.w); lmax = fmaxf(lmax, v.w); }
    }
    for (int o = 16; o; o >>= 1) {
        lmin = fminf(lmin, __shfl_xor_sync(0xffffffffu, lmin, o));
        lmax = fmaxf(lmax, __shfl_xor_sync(0xffffffffu, lmax, o));
        cnt += __shfl_xor_sync(0xffffffffu, cnt, o);
    }
    __shared__ float smn[8], smx[8];
    __shared__ unsigned scn[8];
    int w = threadIdx.x >> 5;
    if ((threadIdx.x & 31) == 0) { smn[w] = lmin; smx[w] = lmax; scn[w] = cnt; }
    __syncthreads();
    if (threadIdx.x == 0) {
        for (int i = 1; i < 8; ++i) {
            lmin = fminf(lmin, smn[i]); lmax = fmaxf(lmax, smx[i]); cnt += scn[i];
        }
        atomicMin(&g_minb1[c], __float_as_uint(lmin));   // nonneg floats: uint order == float order
        atomicMax(&g_maxb1[c], __float_as_uint(lmax));
        atomicAdd(&g_mcnt[c], cnt);
        __threadfence();
        if (atomicInc(&g_ctr1, 4095u) == 4095u) {        // last arriving block; ctr auto-wraps to 0
            for (int ch = 0; ch < NCH; ++ch) {
                unsigned mb = atomicAdd(&g_minb1[ch], 0u);    // L2-coherent reads
                unsigned xb = atomicAdd(&g_maxb1[ch], 0u);
                unsigned mc = atomicAdd(&g_mcnt[ch], 0u);
                float mx = __uint_as_float(xb);
                float mn = __uint_as_float(mb);
                g_cond1[ch] = (mc > 0u) && (mx > 0.0f);
                double sc = 255.0 / fmax((double)mx - (double)mn, 1e-12);
                g_sc1[ch]  = (float)sc;
                g_off1[ch] = (float)(-(double)mn * sc);
                g_minb1[ch] = 0x7f800000u;               // reset for next replay
                g_maxb1[ch] = 0u;                        // (g_mcnt still needed by fin2)
            }
        }
    }
}

// ---------------- K2: normalize, quantize, write bins, tile histograms ---------------
__device__ __forceinline__ unsigned binone(float a, float sc, float off, int cond) {
    float xm = cond ? fmaf(a, sc, off) : 0.0f;
    float x  = a > 0.0f ? xm : a * 255.0f;
    return __float2uint_rz(fminf(x, 255.0f));   // F2I.U32 saturates negatives to 0
}

__global__ __launch_bounds__(256) void k_binhist(const float* __restrict__ X) {
    int tx = blockIdx.x, by = blockIdx.y, c = blockIdx.z;
    int tile = (by >> 3) * 8 + tx;
    __shared__ unsigned sh[NBINS];
    sh[threadIdx.x] = 0u;
    __syncthreads();
    float sc = g_sc1[c], off = g_off1[c];
    int cond = g_cond1[c];
    size_t cb = (size_t)c * NPIX;
#pragma unroll 4
    for (int i = 0; i < 32; ++i) {
        int lin = i * 256 + threadIdx.x;
        int r = lin >> 7, c4 = lin & 127;
        size_t idx = cb + (size_t)(by * 64 + r) * WIDTH + tx * 512 + c4 * 4;
        float4 v = __ldcs(reinterpret_cast<const float4*>(X + idx));
        unsigned b0 = binone(v.x, sc, off, cond);
        unsigned b1 = binone(v.y, sc, off, cond);
        unsigned b2 = binone(v.z, sc, off, cond);
        unsigned b3 = binone(v.w, sc, off, cond);
        atomicAdd(&sh[b0], 1u);
        atomicAdd(&sh[b1], 1u);
        atomicAdd(&sh[b2], 1u);
        atomicAdd(&sh[b3], 1u);
        *reinterpret_cast<unsigned*>(g_xb + idx) = b0 | (b1 << 8) | (b2 << 16) | (b3 << 24);
    }
    __syncthreads();
    atomicAdd(&g_hist[(c * NTILES + tile) * NBINS + threadIdx.x], sh[threadIdx.x]);
}

// ---------------- K3: fused mean-of-nonzeros + per-tile clip/redistribute/scan/LUT ----
__global__ __launch_bounds__(256) void k_lutmean() {
    int c = blockIdx.x >> 6, tile = blockIdx.x & 63, b = threadIdx.x;
    const unsigned* hch = g_hist + c * NTILES * NBINS;

    // channel-wide mean of nonzero bins (recomputed redundantly per block; L2-hit reads)
    unsigned cnt = 0u;
#pragma unroll 8
    for (int t = 0; t < NTILES; ++t) cnt += hch[t * NBINS + b];
    __shared__ unsigned long long ss[NBINS];
    __shared__ unsigned scn[NBINS];
    scn[b] = b ? cnt : 0u;
    ss[b]  = b ? (unsigned long long)cnt * (unsigned)b : 0ull;
    __syncthreads();
    for (int o = 128; o; o >>= 1) {
        if (b < o) { scn[b] += scn[b + o]; ss[b] += ss[b + o]; }
        __syncthreads();
    }
    unsigned nz = scn[0];
    int mean = nz ? (int)(ss[0] / nz) : 0;
    if (b == 0 && tile == 0) g_nzcnt[c] = nz;

    // per-tile clip + redistribute + scan
    int h  = (int)hch[tile * NBINS + b];
    int h0 = (int)hch[tile * NBINS];
    if (nz > 0u) {                 // zero pixels were filled with mean_nz before histogram
        if (b == 0) h = 0;
        if (b == mean) h += h0;
    }
    int hc = min(h, CLIPV);
    int over = h - hc;
    __shared__ int red[NBINS];
    red[b] = over;
    __syncthreads();
    for (int o = 128; o; o >>= 1) {
        if (b < o) red[b] += red[b + o];
        __syncthreads();
    }
    int excess = red[0];
    int batch = excess >> 8;
    int residual = excess & 255;
    int step = residual > 0 ? max(256 / residual, 1) : 256;
    int resadd = ((b % step) == 0 && (b / step) < residual) ? 1 : 0;
    int hf = hc + batch + resadd;
    __shared__ int sc2[NBINS];
    sc2[b] = hf;
    __syncthreads();
    for (int o = 1; o < 256; o <<= 1) {       // Hillis-Steele inclusive scan (exact ints)
        int v = (b >= o) ? sc2[b - o] : 0;
        __syncthreads();
        sc2[b] += v;
        __syncthreads();
    }
    float lut = rintf((float)sc2[b] * LUTF);  // rintf == round-half-even == jnp.round
    lut = fminf(fmaxf(lut, 0.0f), 255.0f);
    g_lut[(c * NTILES + tile) * NBINS + b] = lut;
}

// ---------------- combined 4-point stencil table: one uint per (x-slot, bin) ----------
__device__ __forceinline__ void load_cmb(unsigned (*sl)[NBINS], int c, int tx, int by) {
    int ty = by >> 3;
    int y0 = ((by & 7) < 4) ? max(ty - 1, 0) : ty;
    int y1 = min(y0 + 1, 7);
    const float* L0 = g_lut + ((c * 8 + y0) * 8) * NBINS;
    const float* L1 = g_lut + ((c * 8 + y1) * 8) * NBINS;
    int b = threadIdx.x;   // 256 threads == 256 bins
#pragma unroll
    for (int s = 0; s < 2; ++s) {
        int xa = min(max(tx - 1 + s, 0), 7);
        int xb_ = min(tx + s, 7);
        unsigned v00 = (unsigned)L0[xa * NBINS + b];
        unsigned v10 = (unsigned)L1[xa * NBINS + b];
        unsigned v01 = (unsigned)L0[xb_ * NBINS + b];
        unsigned v11 = (unsigned)L1[xb_ * NBINS + b];
        sl[s][b] = v00 | (v10 << 8) | (v01 << 16) | (v11 << 24);
    }
}

__device__ __forceinline__ float eq4(unsigned w, float wx, float wy, float omy) {
    float v00 = (float)(w & 0xffu);
    float v10 = (float)((w >> 8) & 0xffu);
    float v01 = (float)((w >> 16) & 0xffu);
    float v11 = (float)(w >> 24);
    float ya = omy * v00 + wy * v10;
    float yb = omy * v01 + wy * v11;
    return ya + wx * (yb - ya);
}

// ---------------- K4: min/max of eq + hist re-zero + fused finalize (last block) ------
__global__ __launch_bounds__(256) void k_minmax2() {
    int tx = blockIdx.x, by = blockIdx.y, c = blockIdx.z;
    if (by < 8)                                           // re-zero g_hist for next replay
        g_hist[(c * NTILES + by * 8 + tx) * NBINS + threadIdx.x] = 0u;
    __shared__ unsigned sl[2][NBINS];
    load_cmb(sl, c, tx, by);
    __syncthreads();
    int c4 = threadIdx.x & 127;
    int colb = tx * 512 + c4 * 4;
    float wx[4]; const unsigned* slp[4];
#pragma unroll
    for (int k = 0; k < 4; ++k) {
        float fx = ((float)(colb + k) + 0.5f) * (1.0f / 512.0f) - 0.5f;
        float ff = floorf(fx);
        wx[k] = fx - ff;
        int x0 = min(max((int)ff, 0), 7);
        slp[k] = sl[x0 - tx + 1];
    }
    int r0 = threadIdx.x >> 7;
    size_t base = (size_t)c * NPIX + (size_t)(by * 64 + r0) * WIDTH + colb;
    float emin = __uint_as_float(0x7f800000u), emax = 0.0f;
#pragma unroll 4
    for (int i = 0; i < 32; ++i) {
        int row = by * 64 + i * 2 + r0;
        float fy = ((float)row + 0.5f) * (1.0f / 512.0f) - 0.5f;
        float wy = fy - floorf(fy);
        float omy = 1.0f - wy;
        uchar4 q = *reinterpret_cast<const uchar4*>(g_xb + base + (size_t)i * (2 * WIDTH));
        if (q.x) { float e = eq4(slp[0][q.x], wx[0], wy, omy); emin = fminf(emin, e); emax = fmaxf(emax, e); }
        if (q.y) { float e = eq4(slp[1][q.y], wx[1], wy, omy); emin = fminf(emin, e); emax = fmaxf(emax, e); }
        if (q.z) { float e = eq4(slp[2][q.z], wx[2], wy, omy); emin = fminf(emin, e); emax = fmaxf(emax, e); }
        if (q.w) { float e = eq4(slp[3][q.w], wx[3], wy, omy); emin = fminf(emin, e); emax = fmaxf(emax, e); }
    }
    for (int o = 16; o; o >>= 1) {
        emin = fminf(emin, __shfl_xor_sync(0xffffffffu, emin, o));
        emax = fmaxf(emax, __shfl_xor_sync(0xffffffffu, emax, o));
    }
    __shared__ float smn[8], smx[8];
    int w = threadIdx.x >> 5;
    if ((threadIdx.x & 31) == 0) { smn[w] = emin; smx[w] = emax; }
    __syncthreads();
    if (threadIdx.x == 0) {
        for (int i = 1; i < 8; ++i) { emin = fminf(emin, smn[i]); emax = fmaxf(emax, smx[i]); }
        atomicMin(&g_minb2[c], __float_as_uint(emin));
        atomicMax(&g_maxb2[c], __float_as_uint(emax));
        __threadfence();
        if (atomicInc(&g_ctr2, 2047u) == 2047u) {        // last block; ctr auto-wraps to 0
            for (int ch = 0; ch < NCH; ++ch) {
                unsigned mc = atomicAdd(&g_mcnt[ch], 0u);
                unsigned nz = g_nzcnt[ch];               // written by previous kernel
                float mn = __uint_as_float(atomicAdd(&g_minb2[ch], 0u)) / 255.0f;
                float mx = __uint_as_float(atomicAdd(&g_maxb2[ch], 0u)) / 255.0f;
                if (mc > nz) mn = fminf(mn, 0.0f);       // some masked pixel has eq==0
                int cond = (mc > 0u) && (mx > 0.0f);
                if (cond) {
                    double irng = 1.0 / fmax((double)mx - (double)mn, 1e-12);
                    double fhl = 1.0 - 1.0 / 255.0;
                    g_A[ch] = (float)((1.0 / 255.0) * irng * fhl);
                    g_B[ch] = (float)((1.0 / 255.0) - (double)mn * irng * fhl);
                } else {
                    g_A[ch] = 0.0f;
                    g_B[ch] = INV255;
                }
                g_minb2[ch] = 0x7f800000u;               // reset everything for next replay
                g_maxb2[ch] = 0u;
                g_mcnt[ch]  = 0u;
            }
        }
    }
}

// ---------------- K5: recompute eq, final masked normalize, write output --------------
__global__ __launch_bounds__(256) void k_out(const float* __restrict__ X,
                                             float* __restrict__ out) {
    int tx = blockIdx.x, by = blockIdx.y, c = blockIdx.z;
    __shared__ unsigned sl[2][NBINS];
    load_cmb(sl, c, tx, by);
    __syncthreads();
    float A = g_A[c], B = g_B[c];
    int c4 = threadIdx.x & 127;
    int colb = tx * 512 + c4 * 4;
    float wx[4]; const unsigned* slp[4];
#pragma unroll
    for (int k = 0; k < 4; ++k) {
        float fx = ((float)(colb + k) + 0.5f) * (1.0f / 512.0f) - 0.5f;
        float ff = floorf(fx);
        wx[k] = fx - ff;
        int x0 = min(max((int)ff, 0), 7);
        slp[k] = sl[x0 - tx + 1];
    }
    int r0 = threadIdx.x >> 7;
    size_t base = (size_t)c * NPIX + (size_t)(by * 64 + r0) * WIDTH + colb;
#pragma unroll 4
    for (int i = 0; i < 32; ++i) {
        int row = by * 64 + i * 2 + r0;
        float fy = ((float)row + 0.5f) * (1.0f / 512.0f) - 0.5f;
        float wy = fy - floorf(fy);
        float omy = 1.0f - wy;
        size_t idx = base + (size_t)i * (2 * WIDTH);
        uchar4 q = *reinterpret_cast<const uchar4*>(g_xb + idx);
        float4 o;
        if (min(min(q.x, q.y), min(q.z, q.w)) != 0) {            // fast path: all masked
            o.x = fmaf(eq4(slp[0][q.x], wx[0], wy, omy), A, B);
            o.y = fmaf(eq4(slp[1][q.y], wx[1], wy, omy), A, B);
            o.z = fmaf(eq4(slp[2][q.z], wx[2], wy, omy), A, B);
            o.w = fmaf(eq4(slp[3][q.w], wx[3], wy, omy), A, B);
        } else {                                                  // rare: recover mask from X
            float4 v = *reinterpret_cast<const float4*>(X + idx);
            o.x = q.x ? fmaf(eq4(slp[0][q.x], wx[0], wy, omy), A, B) : (v.x > 0.0f ? B : 0.0f);
            o.y = q.y ? fmaf(eq4(slp[1][q.y], wx[1], wy, omy), A, B) : (v.y > 0.0f ? B : 0.0f);
            o.z = q.z ? fmaf(eq4(slp[2][q.z], wx[2], wy, omy), A, B) : (v.z > 0.0f ? B : 0.0f);
            o.w = q.w ? fmaf(eq4(slp[3][q.w], wx[3], wy, omy), A, B) : (v.w > 0.0f ? B : 0.0f);
        }
        __stcs(reinterpret_cast<float4*>(out + idx), o);          // streaming: never re-read
    }
}

// ---------------- launch --------------------------------------------------------------
extern "C" void kernel_launch(void* const* d_in, const int* in_sizes, int n_in,
                              void* d_out, int out_size) {
    const float* X = (const float*)d_in[0];
    float* out = (float*)d_out;
    (void)in_sizes; (void)n_in; (void)out_size;

    dim3 g(8, 64, NCH);
    k_minmax1<<<4096, 256>>>(X);       // + fused fin1 (last block)
    k_binhist<<<g, 256>>>(X);
    k_lutmean<<<NCH * NTILES, 256>>>();
    k_minmax2<<<g, 256>>>();           // + hist re-zero + fused fin2 (last block)
    k_out<<<g, 256>>>(X, out);
}